// round 7
// baseline (speedup 1.0000x reference)
#include <cuda_runtime.h>
#include <cuda_fp16.h>
#include <cstdint>

#define NPTS 4096
#define NP1  4097
#define PAD  4104           // row stride (elements)
#define NBLK 148            // persistent grid: one block per SM
#define RPB  28             // rows per block (148*28 = 4144 >= 4097)
#define RR   7              // rows per round
#define NRND 4              // rounds per sweep (4*7 = 28)
#define ITERS_OT 100
#define MU_SMALL (1.0f/8192.0f)
#define SCALE_OUT 8192.0f
#define INV_SQRT_D 0.08838834764831845f

// ---------------- device scratch ----------------
__device__ float              g_Ef [(size_t)NP1 * PAD];   // fp32 exp(couplings)
__device__ __half             g_Eh [(size_t)NP1 * PAD];   // fp16 copy (row-major)
__device__ float              g_cs[3][PAD];               // triple-buffered colsums
__device__ float              g_U[PAD];
__device__ float              g_V[PAD];
__device__ float              g_ea;                       // exp(bin_score)
__device__ unsigned long long g_rowbest[NPTS];
__device__ unsigned long long g_colbest[NPTS];
__device__ unsigned           g_arrive;
__device__ volatile unsigned  g_release;

// ---------------- init ----------------
__global__ void init_k(const float* __restrict__ bin) {
    int idx = blockIdx.x * blockDim.x + threadIdx.x;
    float ea = __expf(bin[0]);
    if (idx == 0) { g_arrive = 0; g_release = 0; g_ea = ea; }
    __half eah = __float2half_rn(ea);
    __half zh  = __float2half_rn(0.0f);
    if (idx < PAD) {
        // buf2 = nu  (so first iteration sees V = nu/buf2 = 1)
        float nu = (idx < NPTS) ? MU_SMALL : (idx == NPTS ? 0.5f : 1.0f);
        g_cs[2][idx] = nu;
        g_cs[0][idx] = 0.0f;   // REDG target of iteration 0
        g_cs[1][idx] = 0.0f;
    }
    if (idx < NPTS) g_colbest[idx] = 0ull;
    if (idx < NP1) {
        // bin column and bin row
        g_Ef[(size_t)idx * PAD + NPTS] = ea;
        g_Eh[(size_t)idx * PAD + NPTS] = eah;
        g_Ef[(size_t)NPTS * PAD + idx] = ea;
        g_Eh[(size_t)NPTS * PAD + idx] = eah;
        #pragma unroll
        for (int p = NP1; p < PAD; p++) {
            g_Ef[(size_t)idx * PAD + p] = 0.0f;
            g_Eh[(size_t)idx * PAD + p] = zh;
        }
    }
}

// ---------------- GEMM: C = (A^T B)/sqrt(128); E = exp(C) ----------------
__global__ __launch_bounds__(256) void gemm_exp_k(const float* __restrict__ A,
                                                  const float* __restrict__ B) {
    __shared__ float As[16][128];
    __shared__ float Bs[16][128];
    int tid = threadIdx.x;
    int tx = tid & 15;
    int ty = tid >> 4;
    int n0 = blockIdx.y * 128;
    int m0 = blockIdx.x * 128;

    float acc[8][8];
    #pragma unroll
    for (int i = 0; i < 8; i++)
        #pragma unroll
        for (int j = 0; j < 8; j++) acc[i][j] = 0.0f;

    for (int kk = 0; kk < 128; kk += 16) {
        #pragma unroll
        for (int p = 0; p < 2; p++) {
            int v = tid + p * 256;
            int r = v >> 5;
            int c4 = (v & 31) << 2;
            *(float4*)&As[r][c4] = *(const float4*)&A[(size_t)(kk + r) * 4096 + n0 + c4];
            *(float4*)&Bs[r][c4] = *(const float4*)&B[(size_t)(kk + r) * 4096 + m0 + c4];
        }
        __syncthreads();
        #pragma unroll
        for (int k = 0; k < 16; k++) {
            float a[8], b[8];
            *(float4*)&a[0] = *(float4*)&As[k][ty * 8];
            *(float4*)&a[4] = *(float4*)&As[k][ty * 8 + 4];
            *(float4*)&b[0] = *(float4*)&Bs[k][tx * 8];
            *(float4*)&b[4] = *(float4*)&Bs[k][tx * 8 + 4];
            #pragma unroll
            for (int i = 0; i < 8; i++)
                #pragma unroll
                for (int j = 0; j < 8; j++)
                    acc[i][j] = fmaf(a[i], b[j], acc[i][j]);
        }
        __syncthreads();
    }

    #pragma unroll
    for (int i = 0; i < 8; i++) {
        int n = n0 + ty * 8 + i;
        #pragma unroll
        for (int j = 0; j < 8; j++) {
            int m = m0 + tx * 8 + j;
            float e = __expf(acc[i][j] * INV_SQRT_D);
            g_Ef[(size_t)n * PAD + m] = e;
            g_Eh[(size_t)n * PAD + m] = __float2half_rn(e);
        }
    }
}

// ---------------- fused persistent Sinkhorn ----------------
// Per iteration (single sweep over row-major Eh):
//   V_j = nu_j / colsum_prev[j]   (thread-private, only its 4 owned columns)
//   u_i = mu_i / (E[i,:] . V)     (two-stage block reduce, 7 rows per round)
//   colsum_cur[j] += u_i * E[i,j] (register accumulators -> REDG at sweep end)
__global__ __launch_bounds__(1024, 1) void sink_fused_k() {
    __shared__ float wpart[RR][32];
    __shared__ float u_sh[RR];
    __shared__ float sh_vbin;

    const int tid  = threadIdx.x;
    const int warp = tid >> 5;
    const int lane = tid & 31;
    const int r0   = blockIdx.x * RPB;
    const int col0 = tid * 4;                 // owned columns col0..col0+3 (< 4096)
    const float ea = g_ea;

    for (int k = 0; k < ITERS_OT; k++) {
        const int prev = (k + 2) % 3;
        const int cur  = k % 3;
        const int nxt  = (k + 1) % 3;

        // clear next buffer (disjoint per-block slices; race-free this iteration)
        if (tid < RPB) {
            int c = blockIdx.x * RPB + tid;
            if (c < PAD) g_cs[nxt][c] = 0.0f;
        }
        // private V for owned columns (all owned cols < 4096 -> nu = MU_SMALL)
        float V0 = MU_SMALL / __ldcg(&g_cs[prev][col0 + 0]);
        float V1 = MU_SMALL / __ldcg(&g_cs[prev][col0 + 1]);
        float V2 = MU_SMALL / __ldcg(&g_cs[prev][col0 + 2]);
        float V3 = MU_SMALL / __ldcg(&g_cs[prev][col0 + 3]);
        if (tid == 0) sh_vbin = 0.5f / __ldcg(&g_cs[prev][NPTS]);

        float c0 = 0.0f, c1 = 0.0f, c2 = 0.0f, c3 = 0.0f;
        float blockU = 0.0f;

        // preload round 0 (7 rows x uint2 = 4 halves each)
        uint2 ecur[RR];
        #pragma unroll
        for (int q = 0; q < RR; q++) {
            int row = r0 + q; if (row > NPTS) row = NPTS;
            ecur[q] = *(const uint2*)(g_Eh + (size_t)row * PAD + col0);
        }

        for (int rnd = 0; rnd < NRND; rnd++) {
            // unpack + partial dots
            float f[RR][4], p[RR];
            #pragma unroll
            for (int q = 0; q < RR; q++) {
                float2 a = __half22float2(*(__half2*)&ecur[q].x);
                float2 b = __half22float2(*(__half2*)&ecur[q].y);
                f[q][0] = a.x; f[q][1] = a.y; f[q][2] = b.x; f[q][3] = b.y;
                p[q] = fmaf(a.x, V0, fmaf(a.y, V1, fmaf(b.x, V2, b.y * V3)));
            }
            // preload next round
            uint2 enxt[RR];
            if (rnd < NRND - 1) {
                #pragma unroll
                for (int q = 0; q < RR; q++) {
                    int row = r0 + (rnd + 1) * RR + q; if (row > NPTS) row = NPTS;
                    enxt[q] = *(const uint2*)(g_Eh + (size_t)row * PAD + col0);
                }
            }
            // warp reduce 7 partials
            #pragma unroll
            for (int off = 16; off > 0; off >>= 1)
                #pragma unroll
                for (int q = 0; q < RR; q++)
                    p[q] += __shfl_xor_sync(0xFFFFFFFFu, p[q], off);
            if (lane == 0) {
                #pragma unroll
                for (int q = 0; q < RR; q++) wpart[q][warp] = p[q];
            }
            __syncthreads();
            // stage 2: warps 0..6 finish the 32-way reduce
            if (warp < RR) {
                float v = wpart[warp][lane];
                #pragma unroll
                for (int off = 16; off > 0; off >>= 1)
                    v += __shfl_xor_sync(0xFFFFFFFFu, v, off);
                if (lane == 0) {
                    int row = r0 + rnd * RR + warp;
                    float dot = v + ea * sh_vbin;
                    float mu = (row < NPTS) ? MU_SMALL : (row == NPTS ? 0.5f : 0.0f);
                    float u = mu / dot;          // rows >= NP1 get u = 0
                    u_sh[warp] = u;
                    if (k == ITERS_OT - 1 && row < NP1) g_U[row] = u;
                }
            }
            __syncthreads();
            // accumulate colsums (E still in registers)
            #pragma unroll
            for (int q = 0; q < RR; q++) {
                float uq = u_sh[q];
                c0 = fmaf(uq, f[q][0], c0);
                c1 = fmaf(uq, f[q][1], c1);
                c2 = fmaf(uq, f[q][2], c2);
                c3 = fmaf(uq, f[q][3], c3);
            }
            if (tid == 0) {
                #pragma unroll
                for (int q = 0; q < RR; q++) blockU += u_sh[q];
            }
            #pragma unroll
            for (int q = 0; q < RR; q++) ecur[q] = enxt[q];
        }

        // publish colsums
        atomicAdd(&g_cs[cur][col0 + 0], c0);
        atomicAdd(&g_cs[cur][col0 + 1], c1);
        atomicAdd(&g_cs[cur][col0 + 2], c2);
        atomicAdd(&g_cs[cur][col0 + 3], c3);
        if (tid == 0) atomicAdd(&g_cs[cur][NPTS], ea * blockU);

        // grid barrier
        __syncthreads();
        if (tid == 0) {
            __threadfence();
            unsigned prevn = atomicAdd(&g_arrive, 1);
            if (prevn == (unsigned)(gridDim.x - 1)) {
                g_arrive = 0;
                __threadfence();
                g_release = (unsigned)(k + 1);
            } else {
                while (g_release < (unsigned)(k + 1)) { __nanosleep(40); }
            }
        }
        __syncthreads();
    }
}

// ---------------- finalize V from last colsum buffer ----------------
__global__ void finalize_v_k() {
    int idx = blockIdx.x * blockDim.x + threadIdx.x;
    if (idx < PAD) {
        if (idx < NP1) {
            float nu = (idx < NPTS) ? MU_SMALL : 0.5f;
            g_V[idx] = nu / g_cs[(ITERS_OT - 1) % 3][idx];
        } else {
            g_V[idx] = 0.0f;
        }
    }
}

// ---------------- epilogue: P = Ef*U*V*8192 -> out; row max/argmax ----------------
__global__ __launch_bounds__(256) void epilogue_k(float* __restrict__ out) {
    int i = blockIdx.x;
    int t = threadIdx.x;
    float Ui = g_U[i] * SCALE_OUT;
    unsigned long long best = 0ull;
    for (int j = t; j < NP1; j += 256) {
        float p = g_Ef[(size_t)i * PAD + j] * Ui * g_V[j];
        out[(size_t)i * NP1 + j] = p;
        if (j < NPTS) {
            unsigned long long pk =
                ((unsigned long long)__float_as_uint(p) << 32) | (unsigned)(4095 - j);
            best = (pk > best) ? pk : best;
        }
    }
    __shared__ unsigned long long sb[256];
    sb[t] = best;
    __syncthreads();
    #pragma unroll
    for (int s = 128; s > 0; s >>= 1) {
        if (t < s) { if (sb[t + s] > sb[t]) sb[t] = sb[t + s]; }
        __syncthreads();
    }
    if (t == 0 && i < NPTS) g_rowbest[i] = sb[0];
}

// ---------------- column max/argmax ----------------
__global__ __launch_bounds__(256) void colmax_k(const float* __restrict__ out) {
    int c  = blockIdx.x * 256 + threadIdx.x;
    int i0 = blockIdx.y * 128;
    unsigned long long best = 0ull;
    #pragma unroll 4
    for (int r = 0; r < 128; r++) {
        int i = i0 + r;
        float p = out[(size_t)i * NP1 + c];
        unsigned long long pk =
            ((unsigned long long)__float_as_uint(p) << 32) | (unsigned)(4095 - i);
        best = (pk > best) ? pk : best;
    }
    atomicMax(&g_colbest[c], best);
}

// ---------------- final matching outputs ----------------
__global__ __launch_bounds__(256) void final_k(float* __restrict__ out) {
    int idx = blockIdx.x * 256 + threadIdx.x;
    if (idx >= NPTS) return;
    size_t base = (size_t)NP1 * NP1;

    unsigned long long rb = g_rowbest[idx];
    int   j0   = 4095 - (int)(unsigned)(rb & 0xFFFFFFFFull);
    float maxP = __uint_as_float((unsigned)(rb >> 32));
    unsigned long long cbj = g_colbest[j0];
    int   iback = 4095 - (int)(unsigned)(cbj & 0xFFFFFFFFull);
    bool  mutual0 = (iback == idx);
    float ms0 = mutual0 ? maxP : 0.0f;
    bool  valid0 = mutual0 && (ms0 > 0.2f);
    float idx0f = valid0 ? (float)j0 : -1.0f;

    unsigned long long cb = g_colbest[idx];
    int   i0 = 4095 - (int)(unsigned)(cb & 0xFFFFFFFFull);
    unsigned long long rbi = g_rowbest[i0];
    int   jback = 4095 - (int)(unsigned)(rbi & 0xFFFFFFFFull);
    float rmax  = __uint_as_float((unsigned)(rbi >> 32));
    bool  mutual1 = (jback == idx);
    float ms1 = mutual1 ? rmax : 0.0f;
    bool  valid1 = mutual1 && (rmax > 0.2f);
    float idx1f = valid1 ? (float)i0 : -1.0f;

    out[base + idx]          = idx0f;
    out[base + 4096 + idx]   = idx1f;
    out[base + 8192 + idx]   = ms0;
    out[base + 12288 + idx]  = ms1;
}

// ---------------- launch ----------------
extern "C" void kernel_launch(void* const* d_in, const int* in_sizes, int n_in,
                              void* d_out, int out_size) {
    const float* A   = (const float*)d_in[0];   // mdesc0 (1,128,4096)
    const float* B   = (const float*)d_in[1];   // mdesc1 (1,128,4096)
    const float* bin = (const float*)d_in[2];   // bin_score scalar
    float* out = (float*)d_out;

    init_k<<<17, 256>>>(bin);
    gemm_exp_k<<<dim3(32, 32), 256>>>(A, B);

    sink_fused_k<<<NBLK, 1024>>>();             // 100 fused iterations, one launch

    finalize_v_k<<<17, 256>>>();
    epilogue_k<<<NP1, 256>>>(out);
    colmax_k<<<dim3(16, 32), 256>>>(out);
    final_k<<<16, 256>>>(out);
}

// round 10
// speedup vs baseline: 1.0308x; 1.0308x over previous
#include <cuda_runtime.h>
#include <cuda_fp16.h>
#include <cstdint>

#define NPTS 4096
#define NP1  4097
#define PAD  4104           // row stride (elements) for global E arrays
#define NBLK 148            // persistent grid: one block per SM
#define RPB  28             // rows per block (148*28 = 4144 >= 4097)
#define RR   7              // rows per round
#define NRND 4              // rounds per sweep
#define ITERS_OT 100
#define MU_SMALL (1.0f/8192.0f)
#define SCALE_OUT 8192.0f
#define INV_SQRT_D 0.08838834764831845f

// shared-memory layout for the sink kernel (dynamic)
#define ESH_BYTES   (RPB * 4096 * 2)            // 229376: half E_sh[28][4096]
#define WPART_OFF   ESH_BYTES                   // float wpart[7][33]
#define USH_OFF     (WPART_OFF + 928)           // float u_sh[28]
#define VBIN_OFF    (USH_OFF + RPB * 4)         // float sh_vbin
#define SMEM_SINK   (VBIN_OFF + 16)

// ---------------- device scratch ----------------
__device__ float              g_Ef [(size_t)NP1 * PAD];   // fp32 exp(couplings)
__device__ __half             g_Eh [(size_t)NP1 * PAD];   // fp16 copy (row-major)
__device__ float              g_cs[3][PAD];               // triple-buffered colsums
__device__ float              g_U[PAD];
__device__ float              g_V[PAD];
__device__ float              g_ea;                       // exp(bin_score)
__device__ unsigned long long g_rowbest[NPTS];
__device__ unsigned long long g_colbest[NPTS];
__device__ unsigned           g_arrive;
__device__ volatile unsigned  g_release;

// ---------------- tiny PTX helpers ----------------
__device__ __forceinline__ unsigned long long h2_to_f2(unsigned h2) {
    unsigned long long r;
    asm("{\n\t"
        ".reg .b16 lo_h, hi_h;\n\t"
        ".reg .f32 lo_f, hi_f;\n\t"
        "mov.b32 {lo_h, hi_h}, %1;\n\t"
        "cvt.f32.f16 lo_f, lo_h;\n\t"
        "cvt.f32.f16 hi_f, hi_h;\n\t"
        "mov.b64 %0, {lo_f, hi_f};\n\t"
        "}" : "=l"(r) : "r"(h2));
    return r;
}
__device__ __forceinline__ void fma_f32x2(unsigned long long& acc,
                                          unsigned long long a, unsigned long long b) {
    asm("fma.rn.f32x2 %0, %1, %2, %0;" : "+l"(acc) : "l"(a), "l"(b));
}
__device__ __forceinline__ unsigned long long pack_f2(float lo, float hi) {
    unsigned long long r;
    asm("mov.b64 %0, {%1, %2};" : "=l"(r) : "f"(lo), "f"(hi));
    return r;
}
__device__ __forceinline__ void unpack_f2(unsigned long long v, float& lo, float& hi) {
    asm("mov.b64 {%0, %1}, %2;" : "=f"(lo), "=f"(hi) : "l"(v));
}
__device__ __forceinline__ float warp_sum(float v) {
    #pragma unroll
    for (int o = 16; o > 0; o >>= 1) v += __shfl_xor_sync(0xFFFFFFFFu, v, o);
    return v;
}

// ---------------- init ----------------
__global__ void init_k(const float* __restrict__ bin) {
    int idx = blockIdx.x * blockDim.x + threadIdx.x;
    float ea = __expf(bin[0]);
    if (idx == 0) { g_arrive = 0; g_release = 0; g_ea = ea; }
    __half eah = __float2half_rn(ea);
    __half zh  = __float2half_rn(0.0f);
    if (idx < PAD) {
        float nu = (idx < NPTS) ? MU_SMALL : (idx == NPTS ? 0.5f : 1.0f);
        g_cs[2][idx] = nu;     // so first iteration sees V = 1
        g_cs[0][idx] = 0.0f;
        g_cs[1][idx] = 0.0f;
    }
    if (idx < NPTS) g_colbest[idx] = 0ull;
    if (idx < NP1) {
        g_Ef[(size_t)idx * PAD + NPTS] = ea;
        g_Eh[(size_t)idx * PAD + NPTS] = eah;
        g_Ef[(size_t)NPTS * PAD + idx] = ea;
        g_Eh[(size_t)NPTS * PAD + idx] = eah;
        #pragma unroll
        for (int p = NP1; p < PAD; p++) {
            g_Ef[(size_t)idx * PAD + p] = 0.0f;
            g_Eh[(size_t)idx * PAD + p] = zh;
        }
    }
}

// ---------------- GEMM: C = (A^T B)/sqrt(128); E = exp(C) ----------------
__global__ __launch_bounds__(256) void gemm_exp_k(const float* __restrict__ A,
                                                  const float* __restrict__ B) {
    __shared__ float As[16][128];
    __shared__ float Bs[16][128];
    int tid = threadIdx.x;
    int tx = tid & 15;
    int ty = tid >> 4;
    int n0 = blockIdx.y * 128;
    int m0 = blockIdx.x * 128;

    float acc[8][8];
    #pragma unroll
    for (int i = 0; i < 8; i++)
        #pragma unroll
        for (int j = 0; j < 8; j++) acc[i][j] = 0.0f;

    for (int kk = 0; kk < 128; kk += 16) {
        #pragma unroll
        for (int p = 0; p < 2; p++) {
            int v = tid + p * 256;
            int r = v >> 5;
            int c4 = (v & 31) << 2;
            *(float4*)&As[r][c4] = *(const float4*)&A[(size_t)(kk + r) * 4096 + n0 + c4];
            *(float4*)&Bs[r][c4] = *(const float4*)&B[(size_t)(kk + r) * 4096 + m0 + c4];
        }
        __syncthreads();
        #pragma unroll
        for (int k = 0; k < 16; k++) {
            float a[8], b[8];
            *(float4*)&a[0] = *(float4*)&As[k][ty * 8];
            *(float4*)&a[4] = *(float4*)&As[k][ty * 8 + 4];
            *(float4*)&b[0] = *(float4*)&Bs[k][tx * 8];
            *(float4*)&b[4] = *(float4*)&Bs[k][tx * 8 + 4];
            #pragma unroll
            for (int i = 0; i < 8; i++)
                #pragma unroll
                for (int j = 0; j < 8; j++)
                    acc[i][j] = fmaf(a[i], b[j], acc[i][j]);
        }
        __syncthreads();
    }

    #pragma unroll
    for (int i = 0; i < 8; i++) {
        int n = n0 + ty * 8 + i;
        #pragma unroll
        for (int j = 0; j < 8; j++) {
            int m = m0 + tx * 8 + j;
            float e = __expf(acc[i][j] * INV_SQRT_D);
            g_Ef[(size_t)n * PAD + m] = e;
            g_Eh[(size_t)n * PAD + m] = __float2half_rn(e);
        }
    }
}

// ---------------- persistent fused Sinkhorn, E resident in SMEM ----------------
__global__ __launch_bounds__(1024, 1) void sink_smem_k() {
    extern __shared__ char smem_raw[];
    __half* E_sh    = (__half*)smem_raw;                      // [28][4096]
    float* wpart    = (float*)(smem_raw + WPART_OFF);         // [7][33]
    float* u_sh     = (float*)(smem_raw + USH_OFF);           // [28]
    float* sh_vbin  = (float*)(smem_raw + VBIN_OFF);

    const int tid  = threadIdx.x;
    const int warp = tid >> 5;
    const int lane = tid & 31;
    const int bid  = blockIdx.x;
    const int r0   = bid * RPB;
    const int col0 = tid * 4;
    const float ea = g_ea;

    // ---- one-time: stage this block's 28-row E slice into SMEM ----
    #pragma unroll
    for (int q = 0; q < RPB; q++) {
        int gr = r0 + q; if (gr > NPTS) gr = NPTS;            // clamp (u=0 later)
        uint2 v = *(const uint2*)(g_Eh + (size_t)gr * PAD + col0);
        *(uint2*)((char*)E_sh + (size_t)q * 8192 + tid * 8) = v;
    }
    __syncthreads();

    for (int k = 0; k < ITERS_OT; k++) {
        const int prev = (k + 2) % 3;
        const int cur  = k % 3;
        const int nxt  = (k + 1) % 3;

        // clear next colsum buffer (disjoint per-block slices)
        if (tid < RPB) {
            int c = bid * RPB + tid;
            if (c < PAD) g_cs[nxt][c] = 0.0f;
        }
        // private V for owned columns (all < 4096 -> nu = MU_SMALL)
        float cv0 = __ldcg(&g_cs[prev][col0 + 0]);
        float cv1 = __ldcg(&g_cs[prev][col0 + 1]);
        float cv2 = __ldcg(&g_cs[prev][col0 + 2]);
        float cv3 = __ldcg(&g_cs[prev][col0 + 3]);
        unsigned long long V01 = pack_f2(__fdividef(MU_SMALL, cv0), __fdividef(MU_SMALL, cv1));
        unsigned long long V23 = pack_f2(__fdividef(MU_SMALL, cv2), __fdividef(MU_SMALL, cv3));
        if (tid == 0) *sh_vbin = __fdividef(0.5f, __ldcg(&g_cs[prev][NPTS]));

        unsigned long long cs01 = 0ull, cs23 = 0ull;          // colsum accumulators {f,f}

        for (int rnd = 0; rnd < NRND; rnd++) {
            // load 7 rows' owned 4 columns from SMEM (packed half2 x2)
            uint2 e[RR];
            #pragma unroll
            for (int q = 0; q < RR; q++)
                e[q] = *(const uint2*)((char*)E_sh + (size_t)(rnd * RR + q) * 8192 + tid * 8);

            // partial dots (f32x2) + warp shfl reduction (7 rows pipeline)
            float p[RR];
            #pragma unroll
            for (int q = 0; q < RR; q++) {
                unsigned long long acc = 0ull;
                fma_f32x2(acc, h2_to_f2(e[q].x), V01);
                fma_f32x2(acc, h2_to_f2(e[q].y), V23);
                float lo, hi; unpack_f2(acc, lo, hi);
                p[q] = lo + hi;
            }
            #pragma unroll
            for (int o = 16; o > 0; o >>= 1)
                #pragma unroll
                for (int q = 0; q < RR; q++)
                    p[q] += __shfl_xor_sync(0xFFFFFFFFu, p[q], o);
            if (lane == 0) {
                #pragma unroll
                for (int q = 0; q < RR; q++) wpart[q * 33 + warp] = p[q];
            }
            __syncthreads();

            // stage 2: warps 0..6 reduce 32 warp-partials each
            if (warp < RR) {
                float v = warp_sum(wpart[warp * 33 + lane]);
                if (lane == 0) {
                    int row = r0 + rnd * RR + warp;
                    float dot = v + ea * (*sh_vbin);
                    float mu = (row < NPTS) ? MU_SMALL : (row == NPTS ? 0.5f : 0.0f);
                    float u = __fdividef(mu, dot);
                    u_sh[rnd * RR + warp] = u;
                    if (k == ITERS_OT - 1 && row < NP1) g_U[row] = u;
                }
            }
            __syncthreads();

            // colsum accumulation (E still in registers, u broadcast from SMEM)
            #pragma unroll
            for (int q = 0; q < RR; q++) {
                float uq = u_sh[rnd * RR + q];
                unsigned long long u2 = pack_f2(uq, uq);
                fma_f32x2(cs01, h2_to_f2(e[q].x), u2);
                fma_f32x2(cs23, h2_to_f2(e[q].y), u2);
            }
        }

        // publish colsums
        float c0, c1, c2, c3;
        unpack_f2(cs01, c0, c1);
        unpack_f2(cs23, c2, c3);
        atomicAdd(&g_cs[cur][col0 + 0], c0);
        atomicAdd(&g_cs[cur][col0 + 1], c1);
        atomicAdd(&g_cs[cur][col0 + 2], c2);
        atomicAdd(&g_cs[cur][col0 + 3], c3);
        if (warp == 0) {
            float uu = (lane < RPB) ? u_sh[lane] : 0.0f;
            uu = warp_sum(uu);
            if (lane == 0) atomicAdd(&g_cs[cur][NPTS], ea * uu);
        }

        // grid barrier
        __syncthreads();
        if (tid == 0) {
            __threadfence();
            unsigned prevn = atomicAdd(&g_arrive, 1);
            if (prevn == (unsigned)(gridDim.x - 1)) {
                g_arrive = 0;
                __threadfence();
                g_release = (unsigned)(k + 1);
            } else {
                while (g_release < (unsigned)(k + 1)) { __nanosleep(40); }
            }
        }
        __syncthreads();
    }
}

// ---------------- finalize V from last colsum buffer ----------------
__global__ void finalize_v_k() {
    int idx = blockIdx.x * blockDim.x + threadIdx.x;
    if (idx < PAD) {
        if (idx < NP1) {
            float nu = (idx < NPTS) ? MU_SMALL : 0.5f;
            g_V[idx] = nu / g_cs[(ITERS_OT - 1) % 3][idx];
        } else {
            g_V[idx] = 0.0f;
        }
    }
}

// ---------------- epilogue: P = Ef*U*V*8192 -> out; row max/argmax ----------------
__global__ __launch_bounds__(256) void epilogue_k(float* __restrict__ out) {
    int i = blockIdx.x;
    int t = threadIdx.x;
    float Ui = g_U[i] * SCALE_OUT;
    unsigned long long best = 0ull;
    for (int j = t; j < NP1; j += 256) {
        float p = g_Ef[(size_t)i * PAD + j] * Ui * g_V[j];
        out[(size_t)i * NP1 + j] = p;
        if (j < NPTS) {
            unsigned long long pk =
                ((unsigned long long)__float_as_uint(p) << 32) | (unsigned)(4095 - j);
            best = (pk > best) ? pk : best;
        }
    }
    __shared__ unsigned long long sb[256];
    sb[t] = best;
    __syncthreads();
    #pragma unroll
    for (int s = 128; s > 0; s >>= 1) {
        if (t < s) { if (sb[t + s] > sb[t]) sb[t] = sb[t + s]; }
        __syncthreads();
    }
    if (t == 0 && i < NPTS) g_rowbest[i] = sb[0];
}

// ---------------- column max/argmax ----------------
__global__ __launch_bounds__(256) void colmax_k(const float* __restrict__ out) {
    int c  = blockIdx.x * 256 + threadIdx.x;
    int i0 = blockIdx.y * 128;
    unsigned long long best = 0ull;
    #pragma unroll 4
    for (int r = 0; r < 128; r++) {
        int i = i0 + r;
        float p = out[(size_t)i * NP1 + c];
        unsigned long long pk =
            ((unsigned long long)__float_as_uint(p) << 32) | (unsigned)(4095 - i);
        best = (pk > best) ? pk : best;
    }
    atomicMax(&g_colbest[c], best);
}

// ---------------- final matching outputs ----------------
__global__ __launch_bounds__(256) void final_k(float* __restrict__ out) {
    int idx = blockIdx.x * 256 + threadIdx.x;
    if (idx >= NPTS) return;
    size_t base = (size_t)NP1 * NP1;

    unsigned long long rb = g_rowbest[idx];
    int   j0   = 4095 - (int)(unsigned)(rb & 0xFFFFFFFFull);
    float maxP = __uint_as_float((unsigned)(rb >> 32));
    unsigned long long cbj = g_colbest[j0];
    int   iback = 4095 - (int)(unsigned)(cbj & 0xFFFFFFFFull);
    bool  mutual0 = (iback == idx);
    float ms0 = mutual0 ? maxP : 0.0f;
    bool  valid0 = mutual0 && (ms0 > 0.2f);
    float idx0f = valid0 ? (float)j0 : -1.0f;

    unsigned long long cb = g_colbest[idx];
    int   i0 = 4095 - (int)(unsigned)(cb & 0xFFFFFFFFull);
    unsigned long long rbi = g_rowbest[i0];
    int   jback = 4095 - (int)(unsigned)(rbi & 0xFFFFFFFFull);
    float rmax  = __uint_as_float((unsigned)(rbi >> 32));
    bool  mutual1 = (jback == idx);
    float ms1 = mutual1 ? rmax : 0.0f;
    bool  valid1 = mutual1 && (rmax > 0.2f);
    float idx1f = valid1 ? (float)i0 : -1.0f;

    out[base + idx]          = idx0f;
    out[base + 4096 + idx]   = idx1f;
    out[base + 8192 + idx]   = ms0;
    out[base + 12288 + idx]  = ms1;
}

// ---------------- launch ----------------
extern "C" void kernel_launch(void* const* d_in, const int* in_sizes, int n_in,
                              void* d_out, int out_size) {
    const float* A   = (const float*)d_in[0];   // mdesc0 (1,128,4096)
    const float* B   = (const float*)d_in[1];   // mdesc1 (1,128,4096)
    const float* bin = (const float*)d_in[2];   // bin_score scalar
    float* out = (float*)d_out;

    cudaFuncSetAttribute(sink_smem_k,
                         cudaFuncAttributeMaxDynamicSharedMemorySize, SMEM_SINK);

    init_k<<<17, 256>>>(bin);
    gemm_exp_k<<<dim3(32, 32), 256>>>(A, B);

    sink_smem_k<<<NBLK, 1024, SMEM_SINK>>>();   // 100 fused iterations, one launch

    finalize_v_k<<<17, 256>>>();
    epilogue_k<<<NP1, 256>>>(out);
    colmax_k<<<dim3(16, 32), 256>>>(out);
    final_k<<<16, 256>>>(out);
}